// round 2
// baseline (speedup 1.0000x reference)
#include <cuda_runtime.h>
#include <cuda_bf16.h>

// Problem constants (GatedMessageGcn_3126736191774)
#define RR   1000          // number of relations (rows of G)
#define DD   100           // feature dim
#define MM   2000000       // num_messages (segments)

// ---------------------------------------------------------------------------
// Device scratch (static globals; no runtime allocation allowed)
// ---------------------------------------------------------------------------
__device__ float g_table[RR * RR];   // sigmoid(G_sender @ G_receiver^T), 4 MB
__device__ float g_denom[MM];        // segment sums, 8 MB

// ---------------------------------------------------------------------------
// Kernel 1: 32x32-tiled GEMM (K=100, both operands K-major) + sigmoid epilogue
//   table[i][j] = sigmoid( sum_k Gs[i][k] * Gr[j][k] )
// 256 threads/block; each thread computes 4 outputs.
// ---------------------------------------------------------------------------
#define KPAD 101

__global__ void gemm_sigmoid_kernel(const float* __restrict__ Gs,
                                    const float* __restrict__ Gr) {
    __shared__ float As[32 * KPAD];   // sender rows   [row][k]
    __shared__ float Bs[32 * KPAD];   // receiver rows [row][k]

    const int tid = threadIdx.x;
    const int i0 = blockIdx.y * 32;
    const int j0 = blockIdx.x * 32;

    for (int idx = tid; idx < 32 * DD; idx += 256) {
        int row = idx / DD;
        int k   = idx % DD;
        int gi = i0 + row;
        int gj = j0 + row;
        As[row * KPAD + k] = (gi < RR) ? Gs[gi * DD + k] : 0.0f;
        Bs[row * KPAD + k] = (gj < RR) ? Gr[gj * DD + k] : 0.0f;
    }
    __syncthreads();

    const int tx = tid & 31;   // output column within tile
    const int ty = tid >> 5;   // rows ty, ty+8, ty+16, ty+24

    float acc0 = 0.f, acc1 = 0.f, acc2 = 0.f, acc3 = 0.f;

    #pragma unroll 4
    for (int k = 0; k < DD; k++) {
        float b = Bs[tx * KPAD + k];            // stride-101: conflict-free
        acc0 += As[(ty     ) * KPAD + k] * b;   // broadcast within warp
        acc1 += As[(ty +  8) * KPAD + k] * b;
        acc2 += As[(ty + 16) * KPAD + k] * b;
        acc3 += As[(ty + 24) * KPAD + k] * b;
    }

    const int j = j0 + tx;
    if (j < RR) {
        int i;
        i = i0 + ty;      if (i < RR) g_table[i * RR + j] = 1.0f / (1.0f + __expf(-acc0));
        i = i0 + ty + 8;  if (i < RR) g_table[i * RR + j] = 1.0f / (1.0f + __expf(-acc1));
        i = i0 + ty + 16; if (i < RR) g_table[i * RR + j] = 1.0f / (1.0f + __expf(-acc2));
        i = i0 + ty + 24; if (i < RR) g_table[i * RR + j] = 1.0f / (1.0f + __expf(-acc3));
    }
}

// ---------------------------------------------------------------------------
// Kernel 2: zero the segment-sum buffer
// ---------------------------------------------------------------------------
__global__ void zero_denom_kernel() {
    int i = blockIdx.x * blockDim.x + threadIdx.x;
    if (i < MM) g_denom[i] = 0.0f;
}

// ---------------------------------------------------------------------------
// Kernel 3 (pass 1): gather gate per edge, store gate -> d_out (scratch),
//   atomicAdd gate into denom[receiver].
//   Index pairs are INT32 on device (harness dtype set has no int64).
// ---------------------------------------------------------------------------
__global__ void edge_pass1_kernel(const int2* __restrict__ rel,
                                  const int2* __restrict__ msg,
                                  float* __restrict__ gates_out,
                                  int E) {
    int e = blockIdx.x * blockDim.x + threadIdx.x;
    if (e >= E) return;

    int2 rp = rel[e];        // (sender_rel, receiver_rel) -- 8B coalesced
    int recv = msg[e].y;     // receiver message index

    float g = g_table[rp.x * RR + rp.y];   // 4 MB table: L2-resident gather

    gates_out[e] = g;
    atomicAdd(&g_denom[recv], g);
}

// ---------------------------------------------------------------------------
// Kernel 4 (pass 2): weights = gate / (denom[recv] + 1e-8)
// ---------------------------------------------------------------------------
__global__ void edge_pass2_kernel(const int2* __restrict__ msg,
                                  float* __restrict__ out, int E) {
    int e = blockIdx.x * blockDim.x + threadIdx.x;
    if (e >= E) return;

    int recv = msg[e].y;
    float g  = out[e];
    float d  = g_denom[recv];              // 8 MB table: L2-resident gather
    out[e] = g / (d + 1e-8f);
}

// ---------------------------------------------------------------------------
// Launch
// ---------------------------------------------------------------------------
extern "C" void kernel_launch(void* const* d_in, const int* in_sizes, int n_in,
                              void* d_out, int out_size) {
    const float* Gs = (const float*)d_in[0];
    const float* Gr = (const float*)d_in[1];
    const int2*  rel = (const int2*)d_in[2];
    const int2*  msg = (const int2*)d_in[3];
    float* out = (float*)d_out;

    int E = in_sizes[2] / 2;   // (E,2) index pairs

    // 1. gate table
    dim3 ggrid((RR + 31) / 32, (RR + 31) / 32);
    gemm_sigmoid_kernel<<<ggrid, 256>>>(Gs, Gr);

    // 2. zero denom
    zero_denom_kernel<<<(MM + 255) / 256, 256>>>();

    // 3. pass 1: gates + segment sum
    int nblk = (E + 255) / 256;
    edge_pass1_kernel<<<nblk, 256>>>(rel, msg, out, E);

    // 4. pass 2: normalize
    edge_pass2_kernel<<<nblk, 256>>>(msg, out, E);
}

// round 4
// speedup vs baseline: 1.0878x; 1.0878x over previous
#include <cuda_runtime.h>
#include <cuda_bf16.h>

// Problem constants (GatedMessageGcn_3126736191774)
#define RR   1000          // number of relations
#define DD   100           // feature dim
#define MM   2000000       // num_messages (segments)
#define EMAX 16000000      // edges

// ---------------------------------------------------------------------------
// Device scratch (static; no runtime allocation allowed)
// ---------------------------------------------------------------------------
__device__ float g_table[RR * RR];   // sigmoid(Gs @ Gr^T), 4 MB (L2-resident)
__device__ float g_denom[MM];        // segment sums, 8 MB   (L2-resident)
__device__ int   g_recv[EMAX];       // compacted receiver idx, 64 MB

// ---------------------------------------------------------------------------
// Kernel 1: 32x32-tiled GEMM (K=100) + sigmoid epilogue
// ---------------------------------------------------------------------------
#define KPAD 101

__global__ void gemm_sigmoid_kernel(const float* __restrict__ Gs,
                                    const float* __restrict__ Gr) {
    __shared__ float As[32 * KPAD];
    __shared__ float Bs[32 * KPAD];

    const int tid = threadIdx.x;
    const int i0 = blockIdx.y * 32;
    const int j0 = blockIdx.x * 32;

    for (int idx = tid; idx < 32 * DD; idx += 256) {
        int row = idx / DD;
        int k   = idx % DD;
        int gi = i0 + row;
        int gj = j0 + row;
        As[row * KPAD + k] = (gi < RR) ? Gs[gi * DD + k] : 0.0f;
        Bs[row * KPAD + k] = (gj < RR) ? Gr[gj * DD + k] : 0.0f;
    }
    __syncthreads();

    const int tx = tid & 31;
    const int ty = tid >> 5;

    float acc0 = 0.f, acc1 = 0.f, acc2 = 0.f, acc3 = 0.f;

    #pragma unroll 4
    for (int k = 0; k < DD; k++) {
        float b = Bs[tx * KPAD + k];
        acc0 += As[(ty     ) * KPAD + k] * b;
        acc1 += As[(ty +  8) * KPAD + k] * b;
        acc2 += As[(ty + 16) * KPAD + k] * b;
        acc3 += As[(ty + 24) * KPAD + k] * b;
    }

    const int j = j0 + tx;
    if (j < RR) {
        int i;
        i = i0 + ty;      if (i < RR) g_table[i * RR + j] = 1.0f / (1.0f + __expf(-acc0));
        i = i0 + ty + 8;  if (i < RR) g_table[i * RR + j] = 1.0f / (1.0f + __expf(-acc1));
        i = i0 + ty + 16; if (i < RR) g_table[i * RR + j] = 1.0f / (1.0f + __expf(-acc2));
        i = i0 + ty + 24; if (i < RR) g_table[i * RR + j] = 1.0f / (1.0f + __expf(-acc3));
    }
}

// ---------------------------------------------------------------------------
// Kernel 2: zero the segment-sum buffer (vectorized; MM % 4 == 0)
// ---------------------------------------------------------------------------
__global__ void zero_denom_kernel() {
    int i = blockIdx.x * blockDim.x + threadIdx.x;
    if (i < MM / 4) reinterpret_cast<float4*>(g_denom)[i] = make_float4(0, 0, 0, 0);
}

// ---------------------------------------------------------------------------
// Kernel 3 (pass 1): 4 edges/thread.
//   gather 4 gates (independent chains -> 4x MLP), store gates (float4) and
//   receivers (int4 into g_recv), 4 REDG atomics into denom.
// ---------------------------------------------------------------------------
__global__ void edge_pass1_kernel(const int4* __restrict__ rel4,
                                  const int4* __restrict__ msg4,
                                  float4* __restrict__ gates4,
                                  int E4) {
    int t = blockIdx.x * blockDim.x + threadIdx.x;
    if (t >= E4) return;

    // 2x int4 = 4 (s,r) pairs
    int4 ra = rel4[2 * t];
    int4 rb = rel4[2 * t + 1];
    int4 ma = msg4[2 * t];
    int4 mb = msg4[2 * t + 1];

    // 4 independent L2 gathers
    float g0 = __ldg(&g_table[ra.x * RR + ra.y]);
    float g1 = __ldg(&g_table[ra.z * RR + ra.w]);
    float g2 = __ldg(&g_table[rb.x * RR + rb.y]);
    float g3 = __ldg(&g_table[rb.z * RR + rb.w]);

    gates4[t] = make_float4(g0, g1, g2, g3);
    reinterpret_cast<int4*>(g_recv)[t] = make_int4(ma.y, ma.w, mb.y, mb.w);

    atomicAdd(&g_denom[ma.y], g0);   // return value unused -> REDG
    atomicAdd(&g_denom[ma.w], g1);
    atomicAdd(&g_denom[mb.y], g2);
    atomicAdd(&g_denom[mb.w], g3);
}

// ---------------------------------------------------------------------------
// Kernel 4 (pass 2): weights = gate / (denom[recv] + 1e-8), 4 edges/thread
// ---------------------------------------------------------------------------
__global__ void edge_pass2_kernel(float4* __restrict__ out4, int E4) {
    int t = blockIdx.x * blockDim.x + threadIdx.x;
    if (t >= E4) return;

    float4 g = out4[t];
    int4   r = reinterpret_cast<const int4*>(g_recv)[t];

    // 4 independent L2 gathers
    float d0 = __ldg(&g_denom[r.x]);
    float d1 = __ldg(&g_denom[r.y]);
    float d2 = __ldg(&g_denom[r.z]);
    float d3 = __ldg(&g_denom[r.w]);

    out4[t] = make_float4(g.x / (d0 + 1e-8f),
                          g.y / (d1 + 1e-8f),
                          g.z / (d2 + 1e-8f),
                          g.w / (d3 + 1e-8f));
}

// ---------------------------------------------------------------------------
// Scalar tail (E % 4 != 0 safety; E=16M so normally empty)
// ---------------------------------------------------------------------------
__global__ void edge_tail_kernel(const int2* __restrict__ rel,
                                 const int2* __restrict__ msg,
                                 float* __restrict__ gates,
                                 int start, int E) {
    int e = start + blockIdx.x * blockDim.x + threadIdx.x;
    if (e >= E) return;
    int2 rp = rel[e];
    int  rv = msg[e].y;
    float g = __ldg(&g_table[rp.x * RR + rp.y]);
    gates[e] = g;
    g_recv[e] = rv;
    atomicAdd(&g_denom[rv], g);
}

__global__ void edge_tail2_kernel(float* __restrict__ out,
                                  int start, int E) {
    int e = start + blockIdx.x * blockDim.x + threadIdx.x;
    if (e >= E) return;
    out[e] = out[e] / (__ldg(&g_denom[g_recv[e]]) + 1e-8f);
}

// ---------------------------------------------------------------------------
// Launch
// ---------------------------------------------------------------------------
extern "C" void kernel_launch(void* const* d_in, const int* in_sizes, int n_in,
                              void* d_out, int out_size) {
    const float* Gs = (const float*)d_in[0];
    const float* Gr = (const float*)d_in[1];
    const int4*  rel4 = (const int4*)d_in[2];
    const int4*  msg4 = (const int4*)d_in[3];
    float* out = (float*)d_out;

    int E  = in_sizes[2] / 2;   // (E,2) index pairs
    int E4 = E / 4;
    int tail = E - E4 * 4;

    // 1. gate table
    dim3 ggrid((RR + 31) / 32, (RR + 31) / 32);
    gemm_sigmoid_kernel<<<ggrid, 256>>>(Gs, Gr);

    // 2. zero denom
    zero_denom_kernel<<<(MM / 4 + 255) / 256, 256>>>();

    // 3. pass 1
    int nblk = (E4 + 255) / 256;
    edge_pass1_kernel<<<nblk, 256>>>(rel4, msg4, (float4*)out, E4);
    if (tail) {
        edge_tail_kernel<<<1, 256>>>((const int2*)d_in[2], (const int2*)d_in[3],
                                     out, E4 * 4, E);
    }

    // 4. pass 2
    edge_pass2_kernel<<<nblk, 256>>>((float4*)out, E4);
    if (tail) {
        edge_tail2_kernel<<<1, 256>>>(out, E4 * 4, E);
    }
}